// round 10
// baseline (speedup 1.0000x reference)
#include <cuda_runtime.h>
#include <cuda_bf16.h>

// Shape (fixed): words (32, 4096, 768) f32, diff (32,4096) [unused],
// W (1,1536) f32, b (1,) f32 -> out (32,1) f32.
#define B 32
#define L 4096
#define H 768
#define TWOH 1536
#define NEGV (-1e30f)

// Chunking: each block owns R rows of one batch.
#define CHUNKS 64               // chunks per batch
#define R (L / CHUNKS)          // 64 rows per chunk
#define NCHUNK (B * CHUNKS)     // 2048 worker blocks (+1 finisher block)

// Per-chunk exports + completion counter.
__device__ float g_cmax[NCHUNK];
__device__ float g_stail[NCHUNK * 5];
__device__ float g_thead[NCHUNK * 5];
__device__ unsigned int g_done = 0;

// ---------------------------------------------------------------------------
// One kernel, NCHUNK+1 blocks.
//  blocks 0..NCHUNK-1: s/t projections (warp-per-8-consecutive-rows, float4
//    streaming, regs<=32), internal windowed max, boundary exports, then ONE
//    red.release.gpu.add (no membar/CCTL.IVALL -> no L1-flush disturbance of
//    co-resident load streams; exports are write-through STG, never L1-dirty).
//  block NCHUNK (bid launched LAST -> only waits on earlier blocks, no
//    deadlock): spin ld.acquire on the counter, then finish all 32 batches
//    (L2-resident) and reset the counter for the next graph replay.
// Boundary pairs chunk c -> c+1: l=R-5+i, l+k=R+j, k=5-i+j in [1,5] <=> j<=i.
// ---------------------------------------------------------------------------
__global__ __launch_bounds__(256) void ww_fused_kernel(
    const float* __restrict__ words,
    const float* __restrict__ W,
    const float* __restrict__ bias,
    float* __restrict__ out)
{
    // ---------------- finisher block ----------------
    if (blockIdx.x == NCHUNK) {
        if (threadIdx.x == 0) {
            unsigned int v;
            do {
                asm volatile("ld.acquire.gpu.u32 %0, [%1];"
                             : "=r"(v) : "l"(&g_done) : "memory");
                if (v < NCHUNK) __nanosleep(256);
            } while (v < NCHUNK);
            g_done = 0;                    // reset for next graph replay
        }
        __syncthreads();                   // broadcast acquire to all threads

        // 256 threads = 32 batches x 8 threads; each thread: 8 chunks.
        const int fb  = threadIdx.x >> 3;  // batch 0..31
        const int sub = threadIdx.x & 7;   // 0..7
        float fm = NEGV;
#pragma unroll
        for (int q = 0; q < CHUNKS / 8; q++) {
            const int lc = sub * (CHUNKS / 8) + q;
            const int cc = fb * CHUNKS + lc;
            fm = fmaxf(fm, g_cmax[cc]);
            if (lc < CHUNKS - 1) {
                float st[5], th[5];
#pragma unroll
                for (int i = 0; i < 5; i++) st[i] = g_stail[cc * 5 + i];
#pragma unroll
                for (int j = 0; j < 5; j++) th[j] = g_thead[(cc + 1) * 5 + j];
#pragma unroll
                for (int i = 0; i < 5; i++)
#pragma unroll
                    for (int j = 0; j < 5; j++)
                        if (j <= i) fm = fmaxf(fm, st[i] + th[j]);
            }
        }
#pragma unroll
        for (int off = 4; off > 0; off >>= 1)
            fm = fmaxf(fm, __shfl_xor_sync(0xFFFFFFFFu, fm, off));
        if (sub == 0)
            out[fb] = fmaxf(0.0f, fm + bias[0]);
        return;
    }

    // ---------------- worker blocks ----------------
    __shared__ float sw[TWOH];       // w1 | w2
    __shared__ float s_sh[R];
    __shared__ float t_sh[R];
    __shared__ float red[8];

    for (int i = threadIdx.x; i < TWOH; i += blockDim.x) sw[i] = W[i];
    __syncthreads();

    const float4* w1v = reinterpret_cast<const float4*>(sw);
    const float4* w2v = reinterpret_cast<const float4*>(sw + H);

    const int c    = blockIdx.x;          // chunk id, 0..NCHUNK-1
    const int b    = c / CHUNKS;
    const int ch   = c % CHUNKS;
    const int row0 = b * L + ch * R;

    const int warp = threadIdx.x >> 5;
    const int lane = threadIdx.x & 31;

    // 8 warps x 8 CONSECUTIVE rows each: linear 24KB stream per warp.
    const float4* wp = reinterpret_cast<const float4*>(
        words + (size_t)(row0 + warp * 8) * H);
    for (int it = 0; it < 8; it++) {
        const int r = warp * 8 + it;
        float s = 0.f, t = 0.f;
#pragma unroll
        for (int i = 0; i < H / 128; i++) {        // 6 steps, 512B/warp/step
            const int idx = lane + i * 32;
            const float4 v  = __ldcs(wp + idx);    // read-once streaming
            const float4 a  = w1v[idx];
            const float4 b2 = w2v[idx];
            s = fmaf(v.x, a.x,  fmaf(v.y, a.y,  fmaf(v.z, a.z,  fmaf(v.w, a.w,  s))));
            t = fmaf(v.x, b2.x, fmaf(v.y, b2.y, fmaf(v.z, b2.z, fmaf(v.w, b2.w, t))));
        }
#pragma unroll
        for (int off = 16; off > 0; off >>= 1) {
            s += __shfl_xor_sync(0xFFFFFFFFu, s, off);
            t += __shfl_xor_sync(0xFFFFFFFFu, t, off);
        }
        if (lane == 0) {
            s_sh[r] = s;
            t_sh[r] = t;
        }
        wp += H / 4;                               // advance one row (3KB)
    }
    __syncthreads();

    // Internal windowed max: threads 0..R-1 each take one l.
    float m = NEGV;
    if (threadIdx.x < R) {
        const int l = threadIdx.x;
        const float sl = s_sh[l];
#pragma unroll
        for (int k = 1; k <= 5; k++)
            if (l + k < R) m = fmaxf(m, sl + t_sh[l + k]);
    }
#pragma unroll
    for (int off = 16; off > 0; off >>= 1)
        m = fmaxf(m, __shfl_xor_sync(0xFFFFFFFFu, m, off));
    if (lane == 0) red[warp] = m;
    __syncthreads();
    if (threadIdx.x == 0) {
        float mm = red[0];
#pragma unroll
        for (int w = 1; w < 8; w++) mm = fmaxf(mm, red[w]);
        g_cmax[c] = mm;
    }
    if (threadIdx.x < 5) {
        g_thead[c * 5 + threadIdx.x] = t_sh[threadIdx.x];
        g_stail[c * 5 + threadIdx.x] = s_sh[R - 5 + threadIdx.x];
    }
    __syncthreads();

    // Release publish: fire-and-forget reduction, no membar, no L1 flush.
    if (threadIdx.x == 0) {
        asm volatile("red.release.gpu.global.add.u32 [%0], %1;"
                     :: "l"(&g_done), "r"(1u) : "memory");
    }
}

extern "C" void kernel_launch(void* const* d_in, const int* in_sizes, int n_in,
                              void* d_out, int out_size)
{
    const float* words = (const float*)d_in[0];
    // d_in[1] = diff : unused by the reference computation
    const float* W     = (const float*)d_in[2];
    const float* bias  = (const float*)d_in[3];
    float* out         = (float*)d_out;

    ww_fused_kernel<<<NCHUNK + 1, 256>>>(words, W, bias, out);
}

// round 11
// speedup vs baseline: 1.1070x; 1.1070x over previous
#include <cuda_runtime.h>
#include <cuda_bf16.h>

// Shape (fixed): words (32, 4096, 768) f32, diff (32,4096) [unused],
// W (1,1536) f32, b (1,) f32 -> out (32,1) f32.
#define B 32
#define L 4096
#define H 768
#define TWOH 1536
#define NEGV (-1e30f)

// Chunking: each block owns R rows of one batch.
#define CHUNKS 64               // chunks per batch
#define R (L / CHUNKS)          // 64 rows per chunk
#define NCHUNK (B * CHUNKS)     // 2048 worker blocks (+1 finisher block)

// Per-chunk exports + completion counter.
__device__ float g_cmax[NCHUNK];
__device__ float g_stail[NCHUNK * 5];
__device__ float g_thead[NCHUNK * 5];
__device__ unsigned int g_done = 0;

// ---------------------------------------------------------------------------
// One kernel, NCHUNK+1 blocks. __launch_bounds__(256, 8) HARD-CAPS regs at 32
// (65536/2048) so the finisher branch cannot inflate the worker path's
// occupancy (R10's confound). Publish is a single red.release.gpu (REDG,
// fire-and-forget, no CCTL.IVALL / L1 flush).
//  blocks 0..NCHUNK-1: s/t projections (warp-per-8-consecutive-rows, float4
//    streaming), internal windowed max, boundary exports, release-publish.
//  block NCHUNK (launched last; no deadlock): spin ld.acquire + nanosleep,
//    then finish all 32 batches (L2-resident) and reset the counter.
// Boundary pairs chunk c -> c+1: l=R-5+i, l+k=R+j, k=5-i+j in [1,5] <=> j<=i.
// ---------------------------------------------------------------------------
__global__ __launch_bounds__(256, 8) void ww_fused_kernel(
    const float* __restrict__ words,
    const float* __restrict__ W,
    const float* __restrict__ bias,
    float* __restrict__ out)
{
    // ---------------- finisher block (runs once; spills OK) ----------------
    if (blockIdx.x == NCHUNK) {
        if (threadIdx.x == 0) {
            unsigned int v;
            do {
                asm volatile("ld.acquire.gpu.u32 %0, [%1];"
                             : "=r"(v) : "l"(&g_done) : "memory");
                if (v < NCHUNK) __nanosleep(256);
            } while (v < NCHUNK);
            g_done = 0;                    // reset for next graph replay
        }
        __syncthreads();                   // publish acquire to all threads

        // 256 threads = 32 batches x 8 threads; each thread: 8 chunks.
        const int fb  = threadIdx.x >> 3;  // batch 0..31
        const int sub = threadIdx.x & 7;   // 0..7
        float fm = NEGV;
        for (int q = 0; q < CHUNKS / 8; q++) {
            const int lc = sub * (CHUNKS / 8) + q;
            const int cc = fb * CHUNKS + lc;
            fm = fmaxf(fm, g_cmax[cc]);
            if (lc < CHUNKS - 1) {
                for (int i = 0; i < 5; i++) {
                    const float st = g_stail[cc * 5 + i];
                    for (int j = 0; j <= i; j++)
                        fm = fmaxf(fm, st + g_thead[(cc + 1) * 5 + j]);
                }
            }
        }
#pragma unroll
        for (int off = 4; off > 0; off >>= 1)
            fm = fmaxf(fm, __shfl_xor_sync(0xFFFFFFFFu, fm, off));
        if (sub == 0)
            out[fb] = fmaxf(0.0f, fm + bias[0]);
        return;
    }

    // ---------------- worker blocks ----------------
    __shared__ float sw[TWOH];       // w1 | w2
    __shared__ float s_sh[R];
    __shared__ float t_sh[R];
    __shared__ float red[8];

    for (int i = threadIdx.x; i < TWOH; i += blockDim.x) sw[i] = W[i];
    __syncthreads();

    const float4* w1v = reinterpret_cast<const float4*>(sw);
    const float4* w2v = reinterpret_cast<const float4*>(sw + H);

    const int c    = blockIdx.x;          // chunk id, 0..NCHUNK-1
    const int b    = c / CHUNKS;
    const int ch   = c % CHUNKS;
    const int row0 = b * L + ch * R;

    const int warp = threadIdx.x >> 5;
    const int lane = threadIdx.x & 31;

    // 8 warps x 8 CONSECUTIVE rows each: linear 24KB stream per warp.
    const float4* wp = reinterpret_cast<const float4*>(
        words + (size_t)(row0 + warp * 8) * H);
    for (int it = 0; it < 8; it++) {
        const int r = warp * 8 + it;
        float s = 0.f, t = 0.f;
#pragma unroll
        for (int i = 0; i < H / 128; i++) {        // 6 steps, 512B/warp/step
            const int idx = lane + i * 32;
            const float4 v  = __ldcs(wp + idx);    // read-once streaming
            const float4 a  = w1v[idx];
            const float4 b2 = w2v[idx];
            s = fmaf(v.x, a.x,  fmaf(v.y, a.y,  fmaf(v.z, a.z,  fmaf(v.w, a.w,  s))));
            t = fmaf(v.x, b2.x, fmaf(v.y, b2.y, fmaf(v.z, b2.z, fmaf(v.w, b2.w, t))));
        }
#pragma unroll
        for (int off = 16; off > 0; off >>= 1) {
            s += __shfl_xor_sync(0xFFFFFFFFu, s, off);
            t += __shfl_xor_sync(0xFFFFFFFFu, t, off);
        }
        if (lane == 0) {
            s_sh[r] = s;
            t_sh[r] = t;
        }
        wp += H / 4;                               // advance one row (3KB)
    }
    __syncthreads();

    // Internal windowed max: threads 0..R-1 each take one l.
    float m = NEGV;
    if (threadIdx.x < R) {
        const int l = threadIdx.x;
        const float sl = s_sh[l];
#pragma unroll
        for (int k = 1; k <= 5; k++)
            if (l + k < R) m = fmaxf(m, sl + t_sh[l + k]);
    }
#pragma unroll
    for (int off = 16; off > 0; off >>= 1)
        m = fmaxf(m, __shfl_xor_sync(0xFFFFFFFFu, m, off));
    if (lane == 0) red[warp] = m;
    __syncthreads();
    if (threadIdx.x == 0) {
        float mm = red[0];
#pragma unroll
        for (int w = 1; w < 8; w++) mm = fmaxf(mm, red[w]);
        g_cmax[c] = mm;
    }
    if (threadIdx.x < 5) {
        g_thead[c * 5 + threadIdx.x] = t_sh[threadIdx.x];
        g_stail[c * 5 + threadIdx.x] = s_sh[R - 5 + threadIdx.x];
    }
    __syncthreads();

    // Release publish: fire-and-forget reduction, no membar, no L1 flush.
    if (threadIdx.x == 0) {
        asm volatile("red.release.gpu.global.add.u32 [%0], %1;"
                     :: "l"(&g_done), "r"(1u) : "memory");
    }
}

extern "C" void kernel_launch(void* const* d_in, const int* in_sizes, int n_in,
                              void* d_out, int out_size)
{
    const float* words = (const float*)d_in[0];
    // d_in[1] = diff : unused by the reference computation
    const float* W     = (const float*)d_in[2];
    const float* bias  = (const float*)d_in[3];
    float* out         = (float*)d_out;

    ww_fused_kernel<<<NCHUNK + 1, 256>>>(words, W, bias, out);
}

// round 12
// speedup vs baseline: 1.1331x; 1.0235x over previous
#include <cuda_runtime.h>
#include <cuda_bf16.h>
#include <cooperative_groups.h>

// Shape (fixed): words (32, 4096, 768) f32, diff (32,4096) [unused],
// W (1,1536) f32, b (1,) f32 -> out (32,1) f32.
#define B 32
#define L 4096
#define H 768
#define TWOH 1536
#define NEGV (-1e30f)

// Chunking: each block owns R rows of one batch. Finer chunks (R=32) halve
// the final-wave straggler spread vs R=64 at identical per-row cost.
#define CHUNKS 128              // chunks per batch
#define R (L / CHUNKS)          // 32 rows per chunk
#define NCHUNK (B * CHUNKS)     // 4096 blocks

// Per-chunk exports.
__device__ float g_cmax[NCHUNK];
__device__ float g_stail[NCHUNK * 5];
__device__ float g_thead[NCHUNK * 5];

// ---------------------------------------------------------------------------
// Kernel 1 (hot, pure: no atomics/fences/publish — every fused variant lost
// 5-8us of streaming throughput: R5/R7/R10/R11): s/t projections, internal
// windowed max, boundary exports. Warp w owns rows [4w, 4w+4) -> one linear
// 12KB stream per warp (R9's proven row-locality win).
// ---------------------------------------------------------------------------
__global__ __launch_bounds__(256) void ww_fused_kernel(
    const float* __restrict__ words,
    const float* __restrict__ W)
{
    __shared__ float sw[TWOH];       // w1 | w2
    __shared__ float s_sh[R];
    __shared__ float t_sh[R];
    __shared__ float red[8];

    for (int i = threadIdx.x; i < TWOH; i += blockDim.x) sw[i] = W[i];
    __syncthreads();

    const float4* w1v = reinterpret_cast<const float4*>(sw);
    const float4* w2v = reinterpret_cast<const float4*>(sw + H);

    const int c    = blockIdx.x;          // chunk id, 0..NCHUNK-1
    const int b    = c / CHUNKS;
    const int ch   = c % CHUNKS;
    const int row0 = b * L + ch * R;

    const int warp = threadIdx.x >> 5;
    const int lane = threadIdx.x & 31;

    // 8 warps x 4 CONSECUTIVE rows each: linear 12KB stream per warp.
    const float4* wp = reinterpret_cast<const float4*>(
        words + (size_t)(row0 + warp * 4) * H);
    for (int it = 0; it < 4; it++) {
        const int r = warp * 4 + it;
        float s = 0.f, t = 0.f;
#pragma unroll
        for (int i = 0; i < H / 128; i++) {        // 6 steps, 512B/warp/step
            const int idx = lane + i * 32;
            const float4 v  = __ldcs(wp + idx);    // read-once streaming
            const float4 a  = w1v[idx];
            const float4 b2 = w2v[idx];
            s = fmaf(v.x, a.x,  fmaf(v.y, a.y,  fmaf(v.z, a.z,  fmaf(v.w, a.w,  s))));
            t = fmaf(v.x, b2.x, fmaf(v.y, b2.y, fmaf(v.z, b2.z, fmaf(v.w, b2.w, t))));
        }
#pragma unroll
        for (int off = 16; off > 0; off >>= 1) {
            s += __shfl_xor_sync(0xFFFFFFFFu, s, off);
            t += __shfl_xor_sync(0xFFFFFFFFu, t, off);
        }
        if (lane == 0) {
            s_sh[r] = s;
            t_sh[r] = t;
        }
        wp += H / 4;                               // advance one row (3KB)
    }
    __syncthreads();

    // Internal windowed max: threads 0..R-1 each take one l.
    float m = NEGV;
    if (threadIdx.x < R) {
        const int l = threadIdx.x;
        const float sl = s_sh[l];
#pragma unroll
        for (int k = 1; k <= 5; k++)
            if (l + k < R) m = fmaxf(m, sl + t_sh[l + k]);
    }
#pragma unroll
    for (int off = 16; off > 0; off >>= 1)
        m = fmaxf(m, __shfl_xor_sync(0xFFFFFFFFu, m, off));
    if (lane == 0) red[warp] = m;
    __syncthreads();
    if (threadIdx.x == 0) {
        // only warp 0's entry matters for rows 0..31 (R=32) but all warps
        // computed NEGV-safe partials; combine all 8 for robustness.
        float mm = red[0];
#pragma unroll
        for (int w = 1; w < 8; w++) mm = fmaxf(mm, red[w]);
        g_cmax[c] = mm;
    }
    if (threadIdx.x < 5) {
        g_thead[c * 5 + threadIdx.x] = t_sh[threadIdx.x];
        g_stail[c * 5 + threadIdx.x] = s_sh[R - 5 + threadIdx.x];
    }
}

// ---------------------------------------------------------------------------
// Kernel 2 (finisher, PDL): one block per batch, 256 threads.
//   threads 0..127   : chunk maxes (one each)
//   threads 128..254 : one boundary each (127 boundaries; 15 pairs each)
// Boundary pairs chunk c -> c+1: l=R-5+i, l+k=R+j, k=5-i+j in [1,5] <=> j<=i.
// ---------------------------------------------------------------------------
__global__ __launch_bounds__(256) void ww_final_kernel(
    const float* __restrict__ bias,
    float* __restrict__ out)
{
    cudaGridDependencySynchronize();   // wait for main kernel's writes

    __shared__ float red[8];
    const int b  = blockIdx.x;
    const int t  = threadIdx.x;
    const int c0 = b * CHUNKS;

    float m = NEGV;
    if (t < CHUNKS) {
        m = g_cmax[c0 + t];
    } else if (t < CHUNKS + CHUNKS - 1) {
        const int c = c0 + (t - CHUNKS);
        float st[5], th[5];
#pragma unroll
        for (int i = 0; i < 5; i++) st[i] = g_stail[c * 5 + i];
#pragma unroll
        for (int j = 0; j < 5; j++) th[j] = g_thead[(c + 1) * 5 + j];
#pragma unroll
        for (int i = 0; i < 5; i++)
#pragma unroll
            for (int j = 0; j < 5; j++)
                if (j <= i) m = fmaxf(m, st[i] + th[j]);
    }

#pragma unroll
    for (int off = 16; off > 0; off >>= 1)
        m = fmaxf(m, __shfl_xor_sync(0xFFFFFFFFu, m, off));
    if ((t & 31) == 0) red[t >> 5] = m;
    __syncthreads();
    if (t == 0) {
        float mm = red[0];
#pragma unroll
        for (int w = 1; w < 8; w++) mm = fmaxf(mm, red[w]);
        out[b] = fmaxf(0.0f, mm + bias[0]);
    }
}

extern "C" void kernel_launch(void* const* d_in, const int* in_sizes, int n_in,
                              void* d_out, int out_size)
{
    const float* words = (const float*)d_in[0];
    // d_in[1] = diff : unused by the reference computation
    const float* W     = (const float*)d_in[2];
    const float* bias  = (const float*)d_in[3];
    float* out         = (float*)d_out;

    ww_fused_kernel<<<NCHUNK, 256>>>(words, W);

    // Finisher with programmatic dependent launch (overlaps launch setup
    // with the main kernel; griddepsync provides ordering + visibility).
    cudaLaunchConfig_t cfg = {};
    cfg.gridDim  = dim3(B, 1, 1);
    cfg.blockDim = dim3(256, 1, 1);
    cfg.dynamicSmemBytes = 0;
    cfg.stream = 0;
    cudaLaunchAttribute attr[1];
    attr[0].id = cudaLaunchAttributeProgrammaticStreamSerialization;
    attr[0].val.programmaticStreamSerializationAllowed = 1;
    cfg.attrs = attr;
    cfg.numAttrs = 1;
    cudaLaunchKernelEx(&cfg, ww_final_kernel, bias, out);
}

// round 13
// speedup vs baseline: 1.1637x; 1.0270x over previous
#include <cuda_runtime.h>
#include <cuda_bf16.h>
#include <cooperative_groups.h>

// Shape (fixed): words (32, 4096, 768) f32, diff (32,4096) [unused],
// W (1,1536) f32, b (1,) f32 -> out (32,1) f32.
#define B 32
#define L 4096
#define H 768
#define TWOH 1536
#define NEGV (-1e30f)

// Chunking: each block owns R rows of one batch. R=64 measured optimal
// (R=128 -> 68.8us, R=64 -> 63.5us, R=32 -> ~67us main phase).
#define CHUNKS 64               // chunks per batch
#define R (L / CHUNKS)          // 64 rows per chunk
#define NCHUNK (B * CHUNKS)     // 2048 blocks

// Per-chunk exports.
__device__ float g_cmax[NCHUNK];
__device__ float g_stail[NCHUNK * 5];
__device__ float g_thead[NCHUNK * 5];

// ---------------------------------------------------------------------------
// Kernel 1 (hot, pure: no atomics/fences — every fused-epilogue variant lost
// 5-8us of streaming throughput): s/t projections, internal windowed max,
// boundary exports. Warp w owns rows [8w, 8w+8) -> one linear 24KB stream per
// warp (proven HBM row-locality win). Ends with griddepcontrol.launch_dependents
// (single instruction, no fence/L1-flush) so the PDL finisher's blocks are
// resident+parked before the primary's last wave drains.
// ---------------------------------------------------------------------------
__global__ __launch_bounds__(256) void ww_fused_kernel(
    const float* __restrict__ words,
    const float* __restrict__ W)
{
    __shared__ float sw[TWOH];       // w1 | w2
    __shared__ float s_sh[R];
    __shared__ float t_sh[R];
    __shared__ float red[8];

    for (int i = threadIdx.x; i < TWOH; i += blockDim.x) sw[i] = W[i];
    __syncthreads();

    const float4* w1v = reinterpret_cast<const float4*>(sw);
    const float4* w2v = reinterpret_cast<const float4*>(sw + H);

    const int c    = blockIdx.x;          // chunk id, 0..NCHUNK-1
    const int b    = c / CHUNKS;
    const int ch   = c % CHUNKS;
    const int row0 = b * L + ch * R;

    const int warp = threadIdx.x >> 5;
    const int lane = threadIdx.x & 31;

    // 8 warps x 8 CONSECUTIVE rows each: linear 24KB stream per warp.
    const float4* wp = reinterpret_cast<const float4*>(
        words + (size_t)(row0 + warp * 8) * H);
    for (int it = 0; it < 8; it++) {
        const int r = warp * 8 + it;
        float s = 0.f, t = 0.f;
#pragma unroll
        for (int i = 0; i < H / 128; i++) {        // 6 steps, 512B/warp/step
            const int idx = lane + i * 32;
            const float4 v  = __ldcs(wp + idx);    // read-once streaming
            const float4 a  = w1v[idx];
            const float4 b2 = w2v[idx];
            s = fmaf(v.x, a.x,  fmaf(v.y, a.y,  fmaf(v.z, a.z,  fmaf(v.w, a.w,  s))));
            t = fmaf(v.x, b2.x, fmaf(v.y, b2.y, fmaf(v.z, b2.z, fmaf(v.w, b2.w, t))));
        }
#pragma unroll
        for (int off = 16; off > 0; off >>= 1) {
            s += __shfl_xor_sync(0xFFFFFFFFu, s, off);
            t += __shfl_xor_sync(0xFFFFFFFFu, t, off);
        }
        if (lane == 0) {
            s_sh[r] = s;
            t_sh[r] = t;
        }
        wp += H / 4;                               // advance one row (3KB)
    }
    __syncthreads();

    // Internal windowed max: threads 0..R-1 each take one l.
    float m = NEGV;
    if (threadIdx.x < R) {
        const int l = threadIdx.x;
        const float sl = s_sh[l];
#pragma unroll
        for (int k = 1; k <= 5; k++)
            if (l + k < R) m = fmaxf(m, sl + t_sh[l + k]);
    }
#pragma unroll
    for (int off = 16; off > 0; off >>= 1)
        m = fmaxf(m, __shfl_xor_sync(0xFFFFFFFFu, m, off));
    if (lane == 0) red[warp] = m;
    __syncthreads();
    if (threadIdx.x == 0) {
        float mm = red[0];
#pragma unroll
        for (int w = 1; w < 8; w++) mm = fmaxf(mm, red[w]);
        g_cmax[c] = mm;
    }
    if (threadIdx.x < 5) {
        g_thead[c * 5 + threadIdx.x] = t_sh[threadIdx.x];
        g_stail[c * 5 + threadIdx.x] = s_sh[R - 5 + threadIdx.x];
    }

    // Order exports before the trigger, then signal dependent launch.
    __syncthreads();
    asm volatile("griddepcontrol.launch_dependents;");
}

// ---------------------------------------------------------------------------
// Kernel 2 (finisher, PDL): one block per batch, 128 threads.
//   threads 0..63   : chunk maxes
//   threads 64..126 : one boundary each (15 pairs; MLP=10 L2-resident loads)
// Boundary pairs chunk c -> c+1: l=R-5+i, l+k=R+j, k=5-i+j in [1,5] <=> j<=i.
// ---------------------------------------------------------------------------
__global__ __launch_bounds__(128) void ww_final_kernel(
    const float* __restrict__ bias,
    float* __restrict__ out)
{
    cudaGridDependencySynchronize();   // park until primary triggers + flush

    __shared__ float red[4];
    const int b  = blockIdx.x;
    const int t  = threadIdx.x;
    const int c0 = b * CHUNKS;

    float m = NEGV;
    if (t < CHUNKS) {
        m = g_cmax[c0 + t];
    } else if (t < 64 + CHUNKS - 1) {
        const int c = c0 + (t - 64);
        float st[5], th[5];
#pragma unroll
        for (int i = 0; i < 5; i++) st[i] = g_stail[c * 5 + i];
#pragma unroll
        for (int j = 0; j < 5; j++) th[j] = g_thead[(c + 1) * 5 + j];
#pragma unroll
        for (int i = 0; i < 5; i++)
#pragma unroll
            for (int j = 0; j < 5; j++)
                if (j <= i) m = fmaxf(m, st[i] + th[j]);
    }

#pragma unroll
    for (int off = 16; off > 0; off >>= 1)
        m = fmaxf(m, __shfl_xor_sync(0xFFFFFFFFu, m, off));
    if ((t & 31) == 0) red[t >> 5] = m;
    __syncthreads();
    if (t == 0) {
        float mm = fmaxf(fmaxf(red[0], red[1]), fmaxf(red[2], red[3]));
        out[b] = fmaxf(0.0f, mm + bias[0]);
    }
}

extern "C" void kernel_launch(void* const* d_in, const int* in_sizes, int n_in,
                              void* d_out, int out_size)
{
    const float* words = (const float*)d_in[0];
    // d_in[1] = diff : unused by the reference computation
    const float* W     = (const float*)d_in[2];
    const float* bias  = (const float*)d_in[3];
    float* out         = (float*)d_out;

    ww_fused_kernel<<<NCHUNK, 256>>>(words, W);

    // Finisher with programmatic dependent launch: primary's explicit
    // launch_dependents lets these blocks launch before the primary drains.
    cudaLaunchConfig_t cfg = {};
    cfg.gridDim  = dim3(B, 1, 1);
    cfg.blockDim = dim3(128, 1, 1);
    cfg.dynamicSmemBytes = 0;
    cfg.stream = 0;
    cudaLaunchAttribute attr[1];
    attr[0].id = cudaLaunchAttributeProgrammaticStreamSerialization;
    attr[0].val.programmaticStreamSerializationAllowed = 1;
    cfg.attrs = attr;
    cfg.numAttrs = 1;
    cudaLaunchKernelEx(&cfg, ww_final_kernel, bias, out);
}